// round 3
// baseline (speedup 1.0000x reference)
#include <cuda_runtime.h>
#include <cstdint>

#define N_NODES 100000
#define N_EDGES 2500000
#define N_GRAPHS 256
#define IN_F 6
#define HID 32
#define EMB 64

// ---------------- scratch (device globals; no allocations) ----------------
__device__ int   g_deg[N_NODES];
__device__ int   g_off[N_NODES + 1];
__device__ int   g_cur[N_NODES];
__device__ int   g_srt[N_EDGES];                         // src ids grouped by dst
__device__ __align__(16) float g_h1[N_NODES * HID];      // relu(layer1) output
__device__ __align__(16) float g_gsum[N_GRAPHS * EMB];   // per-graph sums
__device__ float g_gcnt[N_GRAPHS];

// ---------------- vector reductions ----------------
__device__ __forceinline__ void red_add_v2(float* addr, float a, float b) {
    asm volatile("red.global.add.v2.f32 [%0], {%1,%2};"
                 :: "l"(addr), "f"(a), "f"(b) : "memory");
}
__device__ __forceinline__ void red_add_f32(float* addr, float a) {
    asm volatile("red.global.add.f32 [%0], %1;"
                 :: "l"(addr), "f"(a) : "memory");
}

// ---------------- kernels ----------------

__global__ void k_zero() {
    int i = blockIdx.x * blockDim.x + threadIdx.x;
    if (i < N_NODES) g_deg[i] = 0;
    if (i < N_GRAPHS * EMB) g_gsum[i] = 0.f;
    if (i < N_GRAPHS) g_gcnt[i] = 0.f;
}

// In-degree histogram (4 edges per thread via int4 loads).
__global__ void k_deg(const int* __restrict__ dst) {
    int i = blockIdx.x * blockDim.x + threadIdx.x;
    if (i >= N_EDGES / 4) return;
    int4 d = reinterpret_cast<const int4*>(dst)[i];
    atomicAdd(&g_deg[d.x], 1);
    atomicAdd(&g_deg[d.y], 1);
    atomicAdd(&g_deg[d.z], 1);
    atomicAdd(&g_deg[d.w], 1);
}

// Single-block exclusive scan of degrees -> offsets + cursor init.
__global__ void k_scan() {
    __shared__ int sm[1024];
    int t = threadIdx.x;
    const int PER = (N_NODES + 1023) / 1024;  // 98
    int base = t * PER;
    int lim = min(base + PER, N_NODES);
    int s = 0;
    for (int i = base; i < lim; i++) s += g_deg[i];
    sm[t] = s;
    __syncthreads();
    // Hillis-Steele inclusive scan
    for (int off = 1; off < 1024; off <<= 1) {
        int v = (t >= off) ? sm[t - off] : 0;
        __syncthreads();
        sm[t] += v;
        __syncthreads();
    }
    int run = sm[t] - s;  // exclusive prefix for this thread's range
    for (int i = base; i < lim; i++) {
        g_off[i] = run;
        g_cur[i] = run;
        run += g_deg[i];
    }
    if (t == 0) g_off[N_NODES] = N_EDGES;
}

// Scatter src ids into dst-grouped buckets.
__global__ void k_fill(const int* __restrict__ src, const int* __restrict__ dst) {
    int i = blockIdx.x * blockDim.x + threadIdx.x;
    if (i >= N_EDGES / 4) return;
    int4 s = reinterpret_cast<const int4*>(src)[i];
    int4 d = reinterpret_cast<const int4*>(dst)[i];
    g_srt[atomicAdd(&g_cur[d.x], 1)] = s.x;
    g_srt[atomicAdd(&g_cur[d.y], 1)] = s.y;
    g_srt[atomicAdd(&g_cur[d.z], 1)] = s.z;
    g_srt[atomicAdd(&g_cur[d.w], 1)] = s.w;
}

// Fused layer 1: warp per node. Gather x[neighbors], normalize, GEMM 6->32, relu.
__global__ void k_l1(const float* __restrict__ x,
                     const float* __restrict__ W1,
                     const float* __restrict__ b1) {
    __shared__ float sW[IN_F * HID];
    __shared__ float sb[HID];
    for (int i = threadIdx.x; i < IN_F * HID; i += blockDim.x) sW[i] = W1[i];
    if (threadIdx.x < HID) sb[threadIdx.x] = b1[threadIdx.x];
    __syncthreads();

    int w = threadIdx.x >> 5, lane = threadIdx.x & 31;
    int v = blockIdx.x * 8 + w;
    if (v >= N_NODES) return;
    int beg = g_off[v], end = g_off[v + 1];

    float a0 = 0, a1 = 0, a2 = 0, a3 = 0, a4 = 0, a5 = 0;
    for (int j = beg + lane; j < end; j += 32) {
        int s = g_srt[j];
        const float2* xr = reinterpret_cast<const float2*>(x + (size_t)s * IN_F);
        float2 p = xr[0], q = xr[1], r = xr[2];
        a0 += p.x; a1 += p.y; a2 += q.x; a3 += q.y; a4 += r.x; a5 += r.y;
    }
#pragma unroll
    for (int o = 16; o; o >>= 1) {
        a0 += __shfl_xor_sync(0xffffffffu, a0, o);
        a1 += __shfl_xor_sync(0xffffffffu, a1, o);
        a2 += __shfl_xor_sync(0xffffffffu, a2, o);
        a3 += __shfl_xor_sync(0xffffffffu, a3, o);
        a4 += __shfl_xor_sync(0xffffffffu, a4, o);
        a5 += __shfl_xor_sync(0xffffffffu, a5, o);
    }
    float inv = 1.0f / ((float)(end - beg) + 1.0f);
    const float* xv = x + (size_t)v * IN_F;
    float n0 = (a0 + xv[0]) * inv, n1 = (a1 + xv[1]) * inv, n2 = (a2 + xv[2]) * inv;
    float n3 = (a3 + xv[3]) * inv, n4 = (a4 + xv[4]) * inv, n5 = (a5 + xv[5]) * inv;

    float h = sb[lane];
    h += n0 * sW[0 * HID + lane];
    h += n1 * sW[1 * HID + lane];
    h += n2 * sW[2 * HID + lane];
    h += n3 * sW[3 * HID + lane];
    h += n4 * sW[4 * HID + lane];
    h += n5 * sW[5 * HID + lane];
    g_h1[(size_t)v * HID + lane] = fmaxf(h, 0.f);
}

// Fused layer 2 + pooling: warp per node, 8 lanes/edge (4 edges per iter).
// Gather h1[neighbors], normalize, GEMM 32->64, red into per-graph sums.
__global__ void k_l2(const int* __restrict__ gid,
                     const float* __restrict__ W2,
                     const float* __restrict__ b2) {
    __shared__ float sW[HID * EMB];   // 8 KB
    __shared__ float sb[EMB];
    __shared__ float shn[8][HID];
    for (int i = threadIdx.x; i < HID * EMB; i += blockDim.x) sW[i] = W2[i];
    for (int i = threadIdx.x; i < EMB; i += blockDim.x) sb[i] = b2[i];
    __syncthreads();

    int w = threadIdx.x >> 5, lane = threadIdx.x & 31;
    int v = blockIdx.x * 8 + w;
    if (v >= N_NODES) return;
    int beg = g_off[v], end = g_off[v + 1];
    int chunk = lane & 7;   // owns h-dims [chunk*4, chunk*4+4)
    int slot = lane >> 3;   // which of 4 concurrent edges

    float4 acc = make_float4(0.f, 0.f, 0.f, 0.f);
    for (int j = beg + slot; j < end; j += 4) {
        int s = g_srt[j];
        float4 hv = *reinterpret_cast<const float4*>(g_h1 + (size_t)s * HID + chunk * 4);
        acc.x += hv.x; acc.y += hv.y; acc.z += hv.z; acc.w += hv.w;
    }
#pragma unroll
    for (int o = 8; o <= 16; o <<= 1) {
        acc.x += __shfl_xor_sync(0xffffffffu, acc.x, o);
        acc.y += __shfl_xor_sync(0xffffffffu, acc.y, o);
        acc.z += __shfl_xor_sync(0xffffffffu, acc.z, o);
        acc.w += __shfl_xor_sync(0xffffffffu, acc.w, o);
    }
    float inv = 1.0f / ((float)(end - beg) + 1.0f);
    float4 self = *reinterpret_cast<const float4*>(g_h1 + (size_t)v * HID + chunk * 4);
    if (slot == 0) {
        float4 hn;
        hn.x = (acc.x + self.x) * inv;
        hn.y = (acc.y + self.y) * inv;
        hn.z = (acc.z + self.z) * inv;
        hn.w = (acc.w + self.w) * inv;
        *reinterpret_cast<float4*>(&shn[w][chunk * 4]) = hn;
    }
    __syncwarp();

    // GEMM: each lane computes output columns {2*lane, 2*lane+1}
    float2 o2 = *reinterpret_cast<const float2*>(sb + 2 * lane);
    float o0 = o2.x, o1 = o2.y;
#pragma unroll
    for (int k = 0; k < HID; k++) {
        float hk = shn[w][k];
        float2 wv = reinterpret_cast<const float2*>(sW + k * EMB)[lane];
        o0 += hk * wv.x;
        o1 += hk * wv.y;
    }
    int g = gid[v];
    red_add_v2(g_gsum + (size_t)g * EMB + 2 * lane, o0, o1);
    if (lane == 0) red_add_f32(g_gcnt + g, 1.0f);
}

__global__ void k_final(float* __restrict__ out) {
    int i = blockIdx.x * blockDim.x + threadIdx.x;
    if (i >= N_GRAPHS * EMB) return;
    int g = i / EMB;
    out[i] = g_gsum[i] / fmaxf(g_gcnt[g], 1.0f);
}

// ---------------- launch ----------------
extern "C" void kernel_launch(void* const* d_in, const int* in_sizes, int n_in,
                              void* d_out, int out_size) {
    const float* x   = (const float*)d_in[0];
    const int*   src = (const int*)  d_in[1];
    const int*   dst = (const int*)  d_in[2];
    const int*   gid = (const int*)  d_in[3];
    const float* W1  = (const float*)d_in[4];
    const float* b1  = (const float*)d_in[5];
    const float* W2  = (const float*)d_in[6];
    const float* b2  = (const float*)d_in[7];
    float* out = (float*)d_out;

    const int TB = 256;
    k_zero<<<(N_NODES + TB - 1) / TB, TB>>>();
    k_deg<<<(N_EDGES / 4 + TB - 1) / TB, TB>>>(dst);
    k_scan<<<1, 1024>>>();
    k_fill<<<(N_EDGES / 4 + TB - 1) / TB, TB>>>(src, dst);
    k_l1<<<(N_NODES + 7) / 8, TB>>>(x, W1, b1);
    k_l2<<<(N_NODES + 7) / 8, TB>>>(gid, W2, b2);
    k_final<<<(N_GRAPHS * EMB + TB - 1) / TB, TB>>>(out);
}

// round 4
// speedup vs baseline: 1.0028x; 1.0028x over previous
#include <cuda_runtime.h>
#include <cstdint>

#define N_NODES 100000
#define N_EDGES 2500000
#define N_GRAPHS 256
#define IN_F 6
#define HID 32
#define EMB 64

// ---------------- scratch (device globals; no allocations) ----------------
__device__ int   g_deg[N_NODES];
__device__ int   g_off[N_NODES + 1];
__device__ int   g_cur[N_NODES];
__device__ int   g_srt[N_EDGES];                         // src ids grouped by dst
__device__ __align__(16) float g_h1[N_NODES * HID];      // relu(layer1) output
__device__ __align__(16) float g_gsum[N_GRAPHS * EMB];   // per-graph sums
__device__ float g_gcnt[N_GRAPHS];

// ---------------- vector reductions ----------------
__device__ __forceinline__ void red_add_v2(float* addr, float a, float b) {
    asm volatile("red.global.add.v2.f32 [%0], {%1,%2};"
                 :: "l"(addr), "f"(a), "f"(b) : "memory");
}
__device__ __forceinline__ void red_add_f32(float* addr, float a) {
    asm volatile("red.global.add.f32 [%0], %1;"
                 :: "l"(addr), "f"(a) : "memory");
}

// ---------------- kernels ----------------

__global__ void k_zero() {
    int i = blockIdx.x * blockDim.x + threadIdx.x;
    if (i < N_NODES) g_deg[i] = 0;
    if (i < N_GRAPHS * EMB) g_gsum[i] = 0.f;
    if (i < N_GRAPHS) g_gcnt[i] = 0.f;
}

// In-degree histogram (4 edges per thread via int4 loads).
__global__ void k_deg(const int* __restrict__ dst) {
    int i = blockIdx.x * blockDim.x + threadIdx.x;
    if (i >= N_EDGES / 4) return;
    int4 d = reinterpret_cast<const int4*>(dst)[i];
    atomicAdd(&g_deg[d.x], 1);
    atomicAdd(&g_deg[d.y], 1);
    atomicAdd(&g_deg[d.z], 1);
    atomicAdd(&g_deg[d.w], 1);
}

// Single-block exclusive scan of degrees -> offsets + cursor init.
__global__ void k_scan() {
    __shared__ int sm[1024];
    int t = threadIdx.x;
    const int PER = (N_NODES + 1023) / 1024;  // 98
    int base = t * PER;
    int lim = min(base + PER, N_NODES);
    int s = 0;
    for (int i = base; i < lim; i++) s += g_deg[i];
    sm[t] = s;
    __syncthreads();
    // Hillis-Steele inclusive scan
    for (int off = 1; off < 1024; off <<= 1) {
        int v = (t >= off) ? sm[t - off] : 0;
        __syncthreads();
        sm[t] += v;
        __syncthreads();
    }
    int run = sm[t] - s;  // exclusive prefix for this thread's range
    for (int i = base; i < lim; i++) {
        g_off[i] = run;
        g_cur[i] = run;
        run += g_deg[i];
    }
    if (t == 0) g_off[N_NODES] = N_EDGES;
}

// Scatter src ids into dst-grouped buckets.
__global__ void k_fill(const int* __restrict__ src, const int* __restrict__ dst) {
    int i = blockIdx.x * blockDim.x + threadIdx.x;
    if (i >= N_EDGES / 4) return;
    int4 s = reinterpret_cast<const int4*>(src)[i];
    int4 d = reinterpret_cast<const int4*>(dst)[i];
    g_srt[atomicAdd(&g_cur[d.x], 1)] = s.x;
    g_srt[atomicAdd(&g_cur[d.y], 1)] = s.y;
    g_srt[atomicAdd(&g_cur[d.z], 1)] = s.z;
    g_srt[atomicAdd(&g_cur[d.w], 1)] = s.w;
}

// Fused layer 1: warp per node. Gather x[neighbors], normalize, GEMM 6->32, relu.
__global__ void k_l1(const float* __restrict__ x,
                     const float* __restrict__ W1,
                     const float* __restrict__ b1) {
    __shared__ float sW[IN_F * HID];
    __shared__ float sb[HID];
    for (int i = threadIdx.x; i < IN_F * HID; i += blockDim.x) sW[i] = W1[i];
    if (threadIdx.x < HID) sb[threadIdx.x] = b1[threadIdx.x];
    __syncthreads();

    int w = threadIdx.x >> 5, lane = threadIdx.x & 31;
    int v = blockIdx.x * 8 + w;
    if (v >= N_NODES) return;
    int beg = g_off[v], end = g_off[v + 1];

    float a0 = 0, a1 = 0, a2 = 0, a3 = 0, a4 = 0, a5 = 0;
    for (int j = beg + lane; j < end; j += 32) {
        int s = g_srt[j];
        const float2* xr = reinterpret_cast<const float2*>(x + (size_t)s * IN_F);
        float2 p = xr[0], q = xr[1], r = xr[2];
        a0 += p.x; a1 += p.y; a2 += q.x; a3 += q.y; a4 += r.x; a5 += r.y;
    }
#pragma unroll
    for (int o = 16; o; o >>= 1) {
        a0 += __shfl_xor_sync(0xffffffffu, a0, o);
        a1 += __shfl_xor_sync(0xffffffffu, a1, o);
        a2 += __shfl_xor_sync(0xffffffffu, a2, o);
        a3 += __shfl_xor_sync(0xffffffffu, a3, o);
        a4 += __shfl_xor_sync(0xffffffffu, a4, o);
        a5 += __shfl_xor_sync(0xffffffffu, a5, o);
    }
    float inv = 1.0f / ((float)(end - beg) + 1.0f);
    const float* xv = x + (size_t)v * IN_F;
    float n0 = (a0 + xv[0]) * inv, n1 = (a1 + xv[1]) * inv, n2 = (a2 + xv[2]) * inv;
    float n3 = (a3 + xv[3]) * inv, n4 = (a4 + xv[4]) * inv, n5 = (a5 + xv[5]) * inv;

    float h = sb[lane];
    h += n0 * sW[0 * HID + lane];
    h += n1 * sW[1 * HID + lane];
    h += n2 * sW[2 * HID + lane];
    h += n3 * sW[3 * HID + lane];
    h += n4 * sW[4 * HID + lane];
    h += n5 * sW[5 * HID + lane];
    g_h1[(size_t)v * HID + lane] = fmaxf(h, 0.f);
}

// Fused layer 2 + pooling: warp per node, 8 lanes/edge (4 edges per iter).
// Gather h1[neighbors], normalize, GEMM 32->64, red into per-graph sums.
__global__ void k_l2(const int* __restrict__ gid,
                     const float* __restrict__ W2,
                     const float* __restrict__ b2) {
    __shared__ float sW[HID * EMB];   // 8 KB
    __shared__ float sb[EMB];
    __shared__ float shn[8][HID];
    for (int i = threadIdx.x; i < HID * EMB; i += blockDim.x) sW[i] = W2[i];
    for (int i = threadIdx.x; i < EMB; i += blockDim.x) sb[i] = b2[i];
    __syncthreads();

    int w = threadIdx.x >> 5, lane = threadIdx.x & 31;
    int v = blockIdx.x * 8 + w;
    if (v >= N_NODES) return;
    int beg = g_off[v], end = g_off[v + 1];
    int chunk = lane & 7;   // owns h-dims [chunk*4, chunk*4+4)
    int slot = lane >> 3;   // which of 4 concurrent edges

    float4 acc = make_float4(0.f, 0.f, 0.f, 0.f);
    for (int j = beg + slot; j < end; j += 4) {
        int s = g_srt[j];
        float4 hv = *reinterpret_cast<const float4*>(g_h1 + (size_t)s * HID + chunk * 4);
        acc.x += hv.x; acc.y += hv.y; acc.z += hv.z; acc.w += hv.w;
    }
#pragma unroll
    for (int o = 8; o <= 16; o <<= 1) {
        acc.x += __shfl_xor_sync(0xffffffffu, acc.x, o);
        acc.y += __shfl_xor_sync(0xffffffffu, acc.y, o);
        acc.z += __shfl_xor_sync(0xffffffffu, acc.z, o);
        acc.w += __shfl_xor_sync(0xffffffffu, acc.w, o);
    }
    float inv = 1.0f / ((float)(end - beg) + 1.0f);
    float4 self = *reinterpret_cast<const float4*>(g_h1 + (size_t)v * HID + chunk * 4);
    if (slot == 0) {
        float4 hn;
        hn.x = (acc.x + self.x) * inv;
        hn.y = (acc.y + self.y) * inv;
        hn.z = (acc.z + self.z) * inv;
        hn.w = (acc.w + self.w) * inv;
        *reinterpret_cast<float4*>(&shn[w][chunk * 4]) = hn;
    }
    __syncwarp();

    // GEMM: each lane computes output columns {2*lane, 2*lane+1}
    float2 o2 = *reinterpret_cast<const float2*>(sb + 2 * lane);
    float o0 = o2.x, o1 = o2.y;
#pragma unroll
    for (int k = 0; k < HID; k++) {
        float hk = shn[w][k];
        float2 wv = reinterpret_cast<const float2*>(sW + k * EMB)[lane];
        o0 += hk * wv.x;
        o1 += hk * wv.y;
    }
    int g = gid[v];
    red_add_v2(g_gsum + (size_t)g * EMB + 2 * lane, o0, o1);
    if (lane == 0) red_add_f32(g_gcnt + g, 1.0f);
}

__global__ void k_final(float* __restrict__ out) {
    int i = blockIdx.x * blockDim.x + threadIdx.x;
    if (i >= N_GRAPHS * EMB) return;
    int g = i / EMB;
    out[i] = g_gsum[i] / fmaxf(g_gcnt[g], 1.0f);
}

// ---------------- launch ----------------
extern "C" void kernel_launch(void* const* d_in, const int* in_sizes, int n_in,
                              void* d_out, int out_size) {
    const float* x   = (const float*)d_in[0];
    const int*   src = (const int*)  d_in[1];
    const int*   dst = (const int*)  d_in[2];
    const int*   gid = (const int*)  d_in[3];
    const float* W1  = (const float*)d_in[4];
    const float* b1  = (const float*)d_in[5];
    const float* W2  = (const float*)d_in[6];
    const float* b2  = (const float*)d_in[7];
    float* out = (float*)d_out;

    const int TB = 256;
    k_zero<<<(N_NODES + TB - 1) / TB, TB>>>();
    k_deg<<<(N_EDGES / 4 + TB - 1) / TB, TB>>>(dst);
    k_scan<<<1, 1024>>>();
    k_fill<<<(N_EDGES / 4 + TB - 1) / TB, TB>>>(src, dst);
    k_l1<<<(N_NODES + 7) / 8, TB>>>(x, W1, b1);
    k_l2<<<(N_NODES + 7) / 8, TB>>>(gid, W2, b2);
    k_final<<<(N_GRAPHS * EMB + TB - 1) / TB, TB>>>(out);
}